// round 8
// baseline (speedup 1.0000x reference)
#include <cuda_runtime.h>

#define DIM      64
#define KC       512
#define ROWS     64            // z rows per tile
#define KCHUNK   128           // codebook codes per smem chunk
#define NCHUNK   (KC / KCHUNK)
#define NTHREADS 256
#define ZS_LD    68            // 68*4B stride: 16B-aligned, conflict-free reads
#define ES_LD    132
#define SMEM_FLOATS (DIM*ES_LD + DIM*ZS_LD + KC + ROWS)
#define SMEM_BYTES  (SMEM_FLOATS * 4)

// ---- packed f32x2 helpers (ptxas never emits FFMA2 on its own) ----
#define FMA2(acc, a, b) asm("fma.rn.f32x2 %0, %1, %2, %0;" : "+l"(acc) : "l"(a), "l"(b))
#define DUP2(dst, x)    asm("mov.b64 %0, {%1, %1};" : "=l"(dst) : "r"(x))
#define UNPK(lo, hi, v) asm("mov.b64 {%0, %1}, %2;" : "=r"(lo), "=r"(hi) : "l"(v))

__global__ void __launch_bounds__(NTHREADS, 3)
vq_kernel(const float* __restrict__ z, const float* __restrict__ cb,
          float* __restrict__ out, int n_rows) {
    extern __shared__ __align__(16) float sm[];
    float* ES = sm;                   // [DIM][ES_LD]  codebook chunk, transposed
    float* ZS = ES + DIM * ES_LD;     // [DIM][ZS_LD]  z tile, transposed
    float* CN = ZS + DIM * ZS_LD;     // [KC]          ||e_k||^2
    float* ZN = CN + KC;              // [ROWS]        ||z_r||^2

    const int tid = threadIdx.x;
    const int tx  = tid & 15;         // code group: 8 codes (4 packed pairs)
    const int ty  = tid >> 4;         // row group: 4 rows

    // Codebook norms, reference rounding order (rounded mul, rounded add, d ascending).
    for (int k = tid; k < KC; k += NTHREADS) {
        const float* row = cb + k * DIM;
        float acc = 0.f;
        #pragma unroll 1
        for (int d = 0; d < DIM; d++) {
            float e = row[d];
            acc = __fadd_rn(acc, __fmul_rn(e, e));
        }
        CN[k] = acc;
    }

    const int ntiles = n_rows / ROWS;
    for (int tile = blockIdx.x; tile < ntiles; tile += gridDim.x) {
        __syncthreads();   // prior tile's ZS readers done
        const float4* zt4 = reinterpret_cast<const float4*>(z + (size_t)tile * (ROWS * DIM));
        // Z tile transposed; item map keeps consecutive threads on consecutive rows
        // -> conflict-free STS (gmem over-fetch is irrelevant at 1% dram).
        for (int i = tid; i < ROWS * DIM / 4; i += NTHREADS) {
            int r  = i & (ROWS - 1);
            int c4 = i >> 6;
            float4 v = zt4[r * (DIM / 4) + c4];
            int d0 = c4 * 4;
            ZS[(d0 + 0) * ZS_LD + r] = v.x;
            ZS[(d0 + 1) * ZS_LD + r] = v.y;
            ZS[(d0 + 2) * ZS_LD + r] = v.z;
            ZS[(d0 + 3) * ZS_LD + r] = v.w;
        }
        __syncthreads();
        // Row norms: same sequential rounding chain as reference's sum(z*z).
        if (tid < ROWS) {
            float acc = 0.f;
            #pragma unroll 1
            for (int d = 0; d < DIM; d++) {
                float a = ZS[d * ZS_LD + tid];
                acc = __fadd_rn(acc, __fmul_rn(a, a));
            }
            ZN[tid] = acc;
        }
        // (ZN published by the sync at the top of the chunk loop)

        float minv[4]; int mini[4];
        #pragma unroll
        for (int i = 0; i < 4; i++) { minv[i] = __int_as_float(0x7f800000); mini[i] = 0; }

        #pragma unroll 1
        for (int kc = 0; kc < NCHUNK; kc++) {
            __syncthreads();   // prev chunk's ES readers done (also publishes ZN on kc=0)
            const float4* cbc4 = reinterpret_cast<const float4*>(cb + (size_t)(kc * KCHUNK) * DIM);
            for (int i = tid; i < KCHUNK * DIM / 4; i += NTHREADS) {
                int kl = i & (KCHUNK - 1);
                int c4 = i >> 7;
                float4 v = cbc4[kl * (DIM / 4) + c4];
                int d0 = c4 * 4;
                ES[(d0 + 0) * ES_LD + kl] = v.x;
                ES[(d0 + 1) * ES_LD + kl] = v.y;
                ES[(d0 + 2) * ES_LD + kl] = v.z;
                ES[(d0 + 3) * ES_LD + kl] = v.w;
            }
            __syncthreads();

            // 4x8 microtile: acc2[row][pair] holds codes (2p, 2p+1) packed f32x2.
            unsigned long long acc2[4][4];
            #pragma unroll
            for (int i = 0; i < 4; i++)
                #pragma unroll
                for (int j = 0; j < 4; j++) acc2[i][j] = 0ull;

            const float* zp = ZS + ty * 4;
            const float* ep = ES + tx * 8;
            #pragma unroll 4
            for (int d = 0; d < DIM; d++) {
                float4     a   = *reinterpret_cast<const float4*>(zp + d * ZS_LD);
                ulonglong2 b01 = *reinterpret_cast<const ulonglong2*>(ep + d * ES_LD);
                ulonglong2 b23 = *reinterpret_cast<const ulonglong2*>(ep + d * ES_LD + 4);
                unsigned long long bp[4] = {b01.x, b01.y, b23.x, b23.y};
                float av[4] = {a.x, a.y, a.z, a.w};
                #pragma unroll
                for (int i = 0; i < 4; i++) {
                    unsigned long long ad;
                    DUP2(ad, __float_as_uint(av[i]));
                    #pragma unroll
                    for (int j = 0; j < 4; j++) FMA2(acc2[i][j], ad, bp[j]);
                }
            }

            // Epilogue: s = fl(fl(zn - 2*dot) + cn) — FFMA(-2,dot,zn) is bit-identical
            // to fadd(zn, fmul(-2,dot)) since 2*dot is exact. Ascending k, strict <.
            const int kbase = kc * KCHUNK + tx * 8;
            float cn[8];
            {
                float4 c0 = *reinterpret_cast<const float4*>(CN + kbase);
                float4 c1 = *reinterpret_cast<const float4*>(CN + kbase + 4);
                cn[0] = c0.x; cn[1] = c0.y; cn[2] = c0.z; cn[3] = c0.w;
                cn[4] = c1.x; cn[5] = c1.y; cn[6] = c1.z; cn[7] = c1.w;
            }
            #pragma unroll
            for (int i = 0; i < 4; i++) {
                float zn = ZN[ty * 4 + i];
                #pragma unroll
                for (int j = 0; j < 4; j++) {
                    unsigned int lo, hi;
                    UNPK(lo, hi, acc2[i][j]);
                    float s0 = __fadd_rn(__fmaf_rn(-2.0f, __uint_as_float(lo), zn), cn[2 * j]);
                    float s1 = __fadd_rn(__fmaf_rn(-2.0f, __uint_as_float(hi), zn), cn[2 * j + 1]);
                    if (s0 < minv[i]) { minv[i] = s0; mini[i] = kbase + 2 * j; }
                    if (s1 < minv[i]) { minv[i] = s1; mini[i] = kbase + 2 * j + 1; }
                }
            }
        }

        // Reduce across the 16 code-lanes per row group (lower index wins ties).
        #pragma unroll
        for (int i = 0; i < 4; i++) {
            float v  = minv[i];
            int  idx = mini[i];
            #pragma unroll
            for (int off = 8; off > 0; off >>= 1) {
                float vo = __shfl_xor_sync(0xffffffffu, v, off);
                int   io = __shfl_xor_sync(0xffffffffu, idx, off);
                if (vo < v || (vo == v && io < idx)) { v = vo; idx = io; }
            }
            // Output buffer is float32 — exact for idx <= 511.
            if (tx == 0) out[tile * ROWS + ty * 4 + i] = (float)idx;
        }
    }
}

extern "C" void kernel_launch(void* const* d_in, const int* in_sizes, int n_in,
                              void* d_out, int out_size) {
    int cb_idx = (n_in > 1 && in_sizes[1] == KC * DIM) ? 1 : 0;
    int z_idx  = 1 - cb_idx;
    const float* z  = (const float*)d_in[z_idx];    // z_e_x  [32,4096,64] f32
    const float* cb = (const float*)d_in[cb_idx];   // codebook [512,64]  f32
    int n_rows = in_sizes[z_idx] / DIM;             // 131072

    cudaFuncSetAttribute(vq_kernel, cudaFuncAttributeMaxDynamicSharedMemorySize, SMEM_BYTES);
    vq_kernel<<<444, NTHREADS, SMEM_BYTES>>>(z, cb, (float*)d_out, n_rows);
}

// round 9
// speedup vs baseline: 1.2391x; 1.2391x over previous
#include <cuda_runtime.h>

#define DIM      64
#define KC       512
#define ROWS     64           // z rows per tile
#define KCHUNK   64           // codebook codes per smem chunk
#define NCHUNK   (KC / KCHUNK)
#define NTHREADS 256
#define ZS_LD    68           // 68*4B stride: 16B-aligned, conflict-free
#define ES_LD    68

// ---- packed f32x2 helpers (ptxas never emits FFMA2 on its own) ----
#define FMA2(acc, a, b) asm("fma.rn.f32x2 %0, %1, %2, %0;" : "+l"(acc) : "l"(a), "l"(b))
#define DUP2(dst, x)    asm("mov.b64 %0, {%1, %1};" : "=l"(dst) : "r"(x))
#define UNPK(lo, hi, v) asm("mov.b64 {%0, %1}, %2;" : "=r"(lo), "=r"(hi) : "l"(v))

__global__ void __launch_bounds__(NTHREADS, 3)
vq_kernel(const float* __restrict__ z, const float* __restrict__ cb,
          float* __restrict__ out, int n_rows) {
    __shared__ __align__(16) float ZS[DIM * ZS_LD];   // z tile transposed [d][row]
    __shared__ __align__(16) float ES[DIM * ES_LD];   // cb chunk transposed [d][k]
    __shared__ __align__(16) float CN[KC];            // ||e_k||^2
    __shared__ __align__(16) float ZN[ROWS];          // ||z_r||^2

    const int tid = threadIdx.x;
    const int tx  = tid & 15;     // code lane: 4 codes (2 packed pairs)
    const int ty  = tid >> 4;     // row group: 4 rows

    // Codebook norms, reference rounding order (rounded mul, rounded add, d ascending).
    for (int k = tid; k < KC; k += NTHREADS) {
        const float* row = cb + k * DIM;
        float acc = 0.f;
        #pragma unroll 1
        for (int d = 0; d < DIM; d++) {
            float e = row[d];
            acc = __fadd_rn(acc, __fmul_rn(e, e));
        }
        CN[k] = acc;
    }

    const int ntiles = n_rows / ROWS;
    for (int tile = blockIdx.x; tile < ntiles; tile += gridDim.x) {
        __syncthreads();   // prior tile's ZS readers done; CN visible on first pass
        const float* zt = z + (size_t)tile * (ROWS * DIM);
        // Load z tile transposed into ZS (same pattern as the 358us kernel).
        for (int i = tid; i < ROWS * DIM / 4; i += NTHREADS) {
            float4 v = reinterpret_cast<const float4*>(zt)[i];
            int r  = i >> 4;
            int d0 = (i & 15) * 4;
            ZS[(d0 + 0) * ZS_LD + r] = v.x;
            ZS[(d0 + 1) * ZS_LD + r] = v.y;
            ZS[(d0 + 2) * ZS_LD + r] = v.z;
            ZS[(d0 + 3) * ZS_LD + r] = v.w;
        }
        __syncthreads();
        // Row norms: same sequential rounding chain as reference's sum(z*z).
        if (tid < ROWS) {
            float acc = 0.f;
            #pragma unroll 1
            for (int d = 0; d < DIM; d++) {
                float a = ZS[d * ZS_LD + tid];
                acc = __fadd_rn(acc, __fmul_rn(a, a));
            }
            ZN[tid] = acc;
        }
        // (ZN published by the sync at the top of the chunk loop)

        float minv[4]; int mini[4];
        #pragma unroll
        for (int i = 0; i < 4; i++) { minv[i] = __int_as_float(0x7f800000); mini[i] = 0; }

        #pragma unroll 1
        for (int kc = 0; kc < NCHUNK; kc++) {
            __syncthreads();   // prev chunk's ES readers done (also publishes ZN on kc=0)
            const float* cbc = cb + (size_t)(kc * KCHUNK) * DIM;
            for (int i = tid; i < KCHUNK * DIM / 4; i += NTHREADS) {
                float4 v = reinterpret_cast<const float4*>(cbc)[i];
                int kl = i >> 4;
                int d0 = (i & 15) * 4;
                ES[(d0 + 0) * ES_LD + kl] = v.x;
                ES[(d0 + 1) * ES_LD + kl] = v.y;
                ES[(d0 + 2) * ES_LD + kl] = v.z;
                ES[(d0 + 3) * ES_LD + kl] = v.w;
            }
            __syncthreads();

            // 4x4 microtile, f32x2-packed: acc2[row][pair] = codes (2p, 2p+1).
            // B access ep = ES + tx*4: 16 lanes x 16B contiguous -> conflict-free.
            unsigned long long acc2[4][2];
            #pragma unroll
            for (int i = 0; i < 4; i++) { acc2[i][0] = 0ull; acc2[i][1] = 0ull; }

            const float* zp = ZS + ty * 4;
            const float* ep = ES + tx * 4;
            #pragma unroll 4
            for (int d = 0; d < DIM; d++) {
                float4     a = *reinterpret_cast<const float4*>(zp + d * ZS_LD);
                ulonglong2 b = *reinterpret_cast<const ulonglong2*>(ep + d * ES_LD);
                float av[4] = {a.x, a.y, a.z, a.w};
                #pragma unroll
                for (int i = 0; i < 4; i++) {
                    unsigned long long ad;
                    DUP2(ad, __float_as_uint(av[i]));
                    FMA2(acc2[i][0], ad, b.x);
                    FMA2(acc2[i][1], ad, b.y);
                }
            }

            // Epilogue: s = fl(fl(zn - 2*dot) + cn); FFMA(-2,dot,zn) is bit-identical
            // to fadd(zn, fmul(-2,dot)) since 2*dot is exact. Ascending k, strict <.
            const int kbase = kc * KCHUNK + tx * 4;
            float4 cnv = *reinterpret_cast<const float4*>(CN + kbase);
            float cn[4] = {cnv.x, cnv.y, cnv.z, cnv.w};
            #pragma unroll
            for (int i = 0; i < 4; i++) {
                float zn = ZN[ty * 4 + i];
                #pragma unroll
                for (int j = 0; j < 2; j++) {
                    unsigned int lo, hi;
                    UNPK(lo, hi, acc2[i][j]);
                    float s0 = __fadd_rn(__fmaf_rn(-2.0f, __uint_as_float(lo), zn), cn[2 * j]);
                    float s1 = __fadd_rn(__fmaf_rn(-2.0f, __uint_as_float(hi), zn), cn[2 * j + 1]);
                    if (s0 < minv[i]) { minv[i] = s0; mini[i] = kbase + 2 * j; }
                    if (s1 < minv[i]) { minv[i] = s1; mini[i] = kbase + 2 * j + 1; }
                }
            }
        }

        // Reduce across the 16 code-lanes per row group (lower index wins ties).
        #pragma unroll
        for (int i = 0; i < 4; i++) {
            float v  = minv[i];
            int  idx = mini[i];
            #pragma unroll
            for (int off = 8; off > 0; off >>= 1) {
                float vo = __shfl_xor_sync(0xffffffffu, v, off);
                int   io = __shfl_xor_sync(0xffffffffu, idx, off);
                if (vo < v || (vo == v && io < idx)) { v = vo; idx = io; }
            }
            // Output buffer is float32 — exact for idx <= 511.
            if (tx == 0) out[tile * ROWS + ty * 4 + i] = (float)idx;
        }
    }
}

extern "C" void kernel_launch(void* const* d_in, const int* in_sizes, int n_in,
                              void* d_out, int out_size) {
    int cb_idx = (n_in > 1 && in_sizes[1] == KC * DIM) ? 1 : 0;
    int z_idx  = 1 - cb_idx;
    const float* z  = (const float*)d_in[z_idx];    // z_e_x  [32,4096,64] f32
    const float* cb = (const float*)d_in[cb_idx];   // codebook [512,64]  f32
    int n_rows = in_sizes[z_idx] / DIM;             // 131072

    vq_kernel<<<444, NTHREADS>>>(z, cb, (float*)d_out, n_rows);
}

// round 10
// speedup vs baseline: 1.5317x; 1.2361x over previous
#include <cuda_runtime.h>

#define DIM      64
#define KC       512
#define ROWS     128          // z rows per tile
#define KCHUNK   128          // codebook codes per smem chunk
#define NCHUNK   (KC / KCHUNK)
#define NTHREADS 256
#define ZS_LD    132          // 132*4B: 16B-aligned rows, conflict-free
#define ES_LD    132
#define SMEM_FLOATS (DIM*ZS_LD + DIM*ES_LD + KC + ROWS)
#define SMEM_BYTES  (SMEM_FLOATS * 4)

// ---- packed f32x2 helpers (ptxas never emits FFMA2 on its own) ----
#define FMA2(acc, a, b) asm("fma.rn.f32x2 %0, %1, %2, %0;" : "+l"(acc) : "l"(a), "l"(b))
#define DUP2(dst, x)    asm("mov.b64 %0, {%1, %1};" : "=l"(dst) : "r"(x))
#define UNPK(lo, hi, v) asm("mov.b64 {%0, %1}, %2;" : "=r"(lo), "=r"(hi) : "l"(v))

__global__ void __launch_bounds__(NTHREADS, 2)
vq_kernel(const float* __restrict__ z, const float* __restrict__ cb,
          float* __restrict__ out, int n_rows) {
    extern __shared__ __align__(16) float sm[];
    float* ZS = sm;                   // [DIM][ZS_LD]  z tile transposed
    float* ES = ZS + DIM * ZS_LD;     // [DIM][ES_LD]  cb chunk transposed
    float* CN = ES + DIM * ES_LD;     // [KC]          ||e_k||^2
    float* ZN = CN + KC;              // [ROWS]        ||z_r||^2

    const int tid = threadIdx.x;
    const int cx  = tid & 15;         // code group: 4 f32x2 pairs, strided 32 codes
    const int ry  = tid >> 4;         // row group: 8 rows

    // Codebook norms, reference rounding order (rounded mul, rounded add, d ascending).
    for (int k = tid; k < KC; k += NTHREADS) {
        const float* row = cb + k * DIM;
        float acc = 0.f;
        #pragma unroll 1
        for (int d = 0; d < DIM; d++) {
            float e = row[d];
            acc = __fadd_rn(acc, __fmul_rn(e, e));
        }
        CN[k] = acc;
    }

    const int ntiles = n_rows / ROWS;
    for (int tile = blockIdx.x; tile < ntiles; tile += gridDim.x) {
        __syncthreads();   // prior tile's ZS readers done; CN visible on first pass
        const float4* zt4 = reinterpret_cast<const float4*>(z + (size_t)tile * (ROWS * DIM));
        // Z tile transposed; r-major item map -> conflict-free STS.
        for (int i = tid; i < ROWS * DIM / 4; i += NTHREADS) {
            int r  = i & (ROWS - 1);
            int c4 = i >> 7;
            float4 v = zt4[r * (DIM / 4) + c4];
            int d0 = c4 * 4;
            ZS[(d0 + 0) * ZS_LD + r] = v.x;
            ZS[(d0 + 1) * ZS_LD + r] = v.y;
            ZS[(d0 + 2) * ZS_LD + r] = v.z;
            ZS[(d0 + 3) * ZS_LD + r] = v.w;
        }
        __syncthreads();
        // Row norms: same sequential rounding chain as reference's sum(z*z).
        if (tid < ROWS) {
            float acc = 0.f;
            #pragma unroll 1
            for (int d = 0; d < DIM; d++) {
                float a = ZS[d * ZS_LD + tid];
                acc = __fadd_rn(acc, __fmul_rn(a, a));
            }
            ZN[tid] = acc;
        }
        // (ZN published by the sync at the top of the chunk loop)

        float minv[8]; int mini[8];
        #pragma unroll
        for (int i = 0; i < 8; i++) { minv[i] = __int_as_float(0x7f800000); mini[i] = 0; }

        #pragma unroll 1
        for (int kc = 0; kc < NCHUNK; kc++) {
            __syncthreads();   // prev chunk's ES readers done (also publishes ZN on kc=0)
            const float4* cbc4 =
                reinterpret_cast<const float4*>(cb + (size_t)(kc * KCHUNK) * DIM);
            for (int i = tid; i < KCHUNK * DIM / 4; i += NTHREADS) {
                int kl = i & (KCHUNK - 1);
                int c4 = i >> 7;
                float4 v = cbc4[kl * (DIM / 4) + c4];
                int d0 = c4 * 4;
                ES[(d0 + 0) * ES_LD + kl] = v.x;
                ES[(d0 + 1) * ES_LD + kl] = v.y;
                ES[(d0 + 2) * ES_LD + kl] = v.z;
                ES[(d0 + 3) * ES_LD + kl] = v.w;
            }
            __syncthreads();

            // 8x8 microtile: acc2[row][pair]; pair j = codes (2cx+32j, 2cx+32j+1).
            // B via 4 LDS.64: lanes 0-15 span one contiguous 128B -> conflict-free.
            unsigned long long acc2[8][4];
            #pragma unroll
            for (int i = 0; i < 8; i++)
                #pragma unroll
                for (int j = 0; j < 4; j++) acc2[i][j] = 0ull;

            const float* zp = ZS + ry * 8;
            const float* ep = ES + cx * 2;
            #pragma unroll 2
            for (int d = 0; d < DIM; d++) {
                float4 a0 = *reinterpret_cast<const float4*>(zp + d * ZS_LD);
                float4 a1 = *reinterpret_cast<const float4*>(zp + d * ZS_LD + 4);
                unsigned long long bp[4];
                #pragma unroll
                for (int j = 0; j < 4; j++)
                    bp[j] = *reinterpret_cast<const unsigned long long*>(
                                ep + d * ES_LD + j * 32);
                float av[8] = {a0.x, a0.y, a0.z, a0.w, a1.x, a1.y, a1.z, a1.w};
                #pragma unroll
                for (int i = 0; i < 8; i++) {
                    unsigned long long ad;
                    DUP2(ad, __float_as_uint(av[i]));
                    #pragma unroll
                    for (int j = 0; j < 4; j++) FMA2(acc2[i][j], ad, bp[j]);
                }
            }

            // Epilogue: s = fl(fl(zn - 2*dot) + cn); FFMA(-2,dot,zn) bit-identical since
            // 2*dot is exact. Thread scan is ascending k (j ascending), strict <.
            const int kb = kc * KCHUNK + cx * 2;
            float2 cnp[4];
            #pragma unroll
            for (int j = 0; j < 4; j++)
                cnp[j] = *reinterpret_cast<const float2*>(CN + kb + j * 32);
            #pragma unroll
            for (int i = 0; i < 8; i++) {
                float zn = ZN[ry * 8 + i];
                #pragma unroll
                for (int j = 0; j < 4; j++) {
                    unsigned int lo, hi;
                    UNPK(lo, hi, acc2[i][j]);
                    float s0 = __fadd_rn(__fmaf_rn(-2.0f, __uint_as_float(lo), zn), cnp[j].x);
                    float s1 = __fadd_rn(__fmaf_rn(-2.0f, __uint_as_float(hi), zn), cnp[j].y);
                    int k0 = kb + j * 32;
                    if (s0 < minv[i]) { minv[i] = s0; mini[i] = k0; }
                    if (s1 < minv[i]) { minv[i] = s1; mini[i] = k0 + 1; }
                }
            }
        }

        // Reduce across the 16 cx lanes per row group (lower index wins ties).
        #pragma unroll
        for (int i = 0; i < 8; i++) {
            float v  = minv[i];
            int  idx = mini[i];
            #pragma unroll
            for (int off = 8; off > 0; off >>= 1) {
                float vo = __shfl_xor_sync(0xffffffffu, v, off);
                int   io = __shfl_xor_sync(0xffffffffu, idx, off);
                if (vo < v || (vo == v && io < idx)) { v = vo; idx = io; }
            }
            // Output buffer is float32 — exact for idx <= 511.
            if (cx == 0) out[tile * ROWS + ry * 8 + i] = (float)idx;
        }
    }
}

extern "C" void kernel_launch(void* const* d_in, const int* in_sizes, int n_in,
                              void* d_out, int out_size) {
    int cb_idx = (n_in > 1 && in_sizes[1] == KC * DIM) ? 1 : 0;
    int z_idx  = 1 - cb_idx;
    const float* z  = (const float*)d_in[z_idx];    // z_e_x  [32,4096,64] f32
    const float* cb = (const float*)d_in[cb_idx];   // codebook [512,64]  f32
    int n_rows = in_sizes[z_idx] / DIM;             // 131072

    cudaFuncSetAttribute(vq_kernel, cudaFuncAttributeMaxDynamicSharedMemorySize, SMEM_BYTES);
    vq_kernel<<<296, NTHREADS, SMEM_BYTES>>>(z, cb, (float*)d_out, n_rows);
}

// round 11
// speedup vs baseline: 1.7224x; 1.1245x over previous
#include <cuda_runtime.h>

#define DIM      64
#define KC       512
#define ROWS     128          // z rows per tile
#define KCHUNK   128          // codebook codes per smem chunk
#define NCHUNK   (KC / KCHUNK)
#define NTHREADS 256
#define ZS_LD    132          // 132*4B: 16B-aligned rows, conflict-free
#define ES_LD    132
#define SMEM_FLOATS (DIM*ZS_LD + DIM*ES_LD + KC + ROWS)
#define SMEM_BYTES  (SMEM_FLOATS * 4)

// ---- packed f32x2 helpers (ptxas never emits FFMA2 on its own) ----
#define FMA2(acc, a, b) asm("fma.rn.f32x2 %0, %1, %2, %0;" : "+l"(acc) : "l"(a), "l"(b))
#define DUP2(dst, x)    asm("mov.b64 %0, {%1, %1};" : "=l"(dst) : "r"(x))
#define UNPK(lo, hi, v) asm("mov.b64 {%0, %1}, %2;" : "=r"(lo), "=r"(hi) : "l"(v))

__device__ unsigned int g_tile_ctr;

__global__ void vq_reset() { g_tile_ctr = 0; }

__global__ void __launch_bounds__(NTHREADS, 2)
vq_kernel(const float* __restrict__ z, const float* __restrict__ cb,
          float* __restrict__ out, int n_rows) {
    extern __shared__ __align__(16) float sm[];
    float* ZS = sm;                   // [DIM][ZS_LD]  z tile transposed
    float* ES = ZS + DIM * ZS_LD;     // [DIM][ES_LD]  cb chunk transposed
    float* CN = ES + DIM * ES_LD;     // [KC]          ||e_k||^2
    float* ZN = CN + KC;              // [ROWS]        ||z_r||^2
    __shared__ int s_tile;

    const int tid = threadIdx.x;
    const int cx  = tid & 15;         // code group: 8 codes as 2 float4 spans
    const int ry  = tid >> 4;         // row group: 8 rows

    // Codebook norms, reference rounding order (rounded mul, rounded add, d ascending).
    for (int k = tid; k < KC; k += NTHREADS) {
        const float* row = cb + k * DIM;
        float acc = 0.f;
        #pragma unroll 1
        for (int d = 0; d < DIM; d++) {
            float e = row[d];
            acc = __fadd_rn(acc, __fmul_rn(e, e));
        }
        CN[k] = acc;
    }

    const int ntiles = n_rows / ROWS;
    for (;;) {
        __syncthreads();   // prior tile's readers done; CN visible on first pass
        if (tid == 0) s_tile = (int)atomicAdd(&g_tile_ctr, 1u);
        __syncthreads();
        const int tile = s_tile;
        if (tile >= ntiles) break;

        const float4* zt4 = reinterpret_cast<const float4*>(z + (size_t)tile * (ROWS * DIM));
        // Z tile transposed; r-major item map -> conflict-free STS.
        for (int i = tid; i < ROWS * DIM / 4; i += NTHREADS) {
            int r  = i & (ROWS - 1);
            int c4 = i >> 7;
            float4 v = zt4[r * (DIM / 4) + c4];
            int d0 = c4 * 4;
            ZS[(d0 + 0) * ZS_LD + r] = v.x;
            ZS[(d0 + 1) * ZS_LD + r] = v.y;
            ZS[(d0 + 2) * ZS_LD + r] = v.z;
            ZS[(d0 + 3) * ZS_LD + r] = v.w;
        }
        __syncthreads();
        // Row norms: same sequential rounding chain as reference's sum(z*z).
        if (tid < ROWS) {
            float acc = 0.f;
            #pragma unroll 1
            for (int d = 0; d < DIM; d++) {
                float a = ZS[d * ZS_LD + tid];
                acc = __fadd_rn(acc, __fmul_rn(a, a));
            }
            ZN[tid] = acc;
        }
        // (ZN published by the sync at the top of the chunk loop)

        float minv[8]; int mini[8];
        #pragma unroll
        for (int i = 0; i < 8; i++) { minv[i] = __int_as_float(0x7f800000); mini[i] = 0; }

        #pragma unroll 1
        for (int kc = 0; kc < NCHUNK; kc++) {
            __syncthreads();   // prev chunk's ES readers done (also publishes ZN on kc=0)
            const float4* cbc4 =
                reinterpret_cast<const float4*>(cb + (size_t)(kc * KCHUNK) * DIM);
            for (int i = tid; i < KCHUNK * DIM / 4; i += NTHREADS) {
                int kl = i & (KCHUNK - 1);
                int c4 = i >> 7;
                float4 v = cbc4[kl * (DIM / 4) + c4];
                int d0 = c4 * 4;
                ES[(d0 + 0) * ES_LD + kl] = v.x;
                ES[(d0 + 1) * ES_LD + kl] = v.y;
                ES[(d0 + 2) * ES_LD + kl] = v.z;
                ES[(d0 + 3) * ES_LD + kl] = v.w;
            }
            __syncthreads();

            // 8x8 microtile: codes = {cx*4..cx*4+3} and {64+cx*4..}, each span one
            // LDS.128 (16 lanes x 16B contiguous -> conflict-free). acc2[row][pair]:
            // pairs (0,1),(2,3) of span0 then span1 — ascending k within thread.
            unsigned long long acc2[8][4];
            #pragma unroll
            for (int i = 0; i < 8; i++)
                #pragma unroll
                for (int j = 0; j < 4; j++) acc2[i][j] = 0ull;

            const float* zp = ZS + ry * 8;
            const float* ep = ES + cx * 4;
            #pragma unroll 2
            for (int d = 0; d < DIM; d++) {
                float4 a0 = *reinterpret_cast<const float4*>(zp + d * ZS_LD);
                float4 a1 = *reinterpret_cast<const float4*>(zp + d * ZS_LD + 4);
                ulonglong2 b0 = *reinterpret_cast<const ulonglong2*>(ep + d * ES_LD);
                ulonglong2 b1 = *reinterpret_cast<const ulonglong2*>(ep + d * ES_LD + 64);
                unsigned long long bp[4] = {b0.x, b0.y, b1.x, b1.y};
                float av[8] = {a0.x, a0.y, a0.z, a0.w, a1.x, a1.y, a1.z, a1.w};
                #pragma unroll
                for (int i = 0; i < 8; i++) {
                    unsigned long long ad;
                    DUP2(ad, __float_as_uint(av[i]));
                    #pragma unroll
                    for (int j = 0; j < 4; j++) FMA2(acc2[i][j], ad, bp[j]);
                }
            }

            // Epilogue: s = fl(fl(zn - 2*dot) + cn); FFMA(-2,dot,zn) bit-identical since
            // 2*dot is exact. Thread scan ascending k, strict < keeps first index.
            const int kb = kc * KCHUNK + cx * 4;
            float4 c0 = *reinterpret_cast<const float4*>(CN + kb);
            float4 c1 = *reinterpret_cast<const float4*>(CN + kb + 64);
            float cn[8] = {c0.x, c0.y, c0.z, c0.w, c1.x, c1.y, c1.z, c1.w};
            #pragma unroll
            for (int i = 0; i < 8; i++) {
                float zn = ZN[ry * 8 + i];
                #pragma unroll
                for (int j = 0; j < 4; j++) {
                    unsigned int lo, hi;
                    UNPK(lo, hi, acc2[i][j]);
                    float s0 = __fadd_rn(__fmaf_rn(-2.0f, __uint_as_float(lo), zn), cn[2 * j]);
                    float s1 = __fadd_rn(__fmaf_rn(-2.0f, __uint_as_float(hi), zn), cn[2 * j + 1]);
                    int k0 = kb + (j >> 1) * 64 + (j & 1) * 2;
                    if (s0 < minv[i]) { minv[i] = s0; mini[i] = k0; }
                    if (s1 < minv[i]) { minv[i] = s1; mini[i] = k0 + 1; }
                }
            }
        }

        // Reduce across the 16 cx lanes per row group (lower index wins ties).
        #pragma unroll
        for (int i = 0; i < 8; i++) {
            float v  = minv[i];
            int  idx = mini[i];
            #pragma unroll
            for (int off = 8; off > 0; off >>= 1) {
                float vo = __shfl_xor_sync(0xffffffffu, v, off);
                int   io = __shfl_xor_sync(0xffffffffu, idx, off);
                if (vo < v || (vo == v && io < idx)) { v = vo; idx = io; }
            }
            // Output buffer is float32 — exact for idx <= 511.
            if (cx == 0) out[tile * ROWS + ry * 8 + i] = (float)idx;
        }
    }
}

extern "C" void kernel_launch(void* const* d_in, const int* in_sizes, int n_in,
                              void* d_out, int out_size) {
    int cb_idx = (n_in > 1 && in_sizes[1] == KC * DIM) ? 1 : 0;
    int z_idx  = 1 - cb_idx;
    const float* z  = (const float*)d_in[z_idx];    // z_e_x  [32,4096,64] f32
    const float* cb = (const float*)d_in[cb_idx];   // codebook [512,64]  f32
    int n_rows = in_sizes[z_idx] / DIM;             // 131072

    cudaFuncSetAttribute(vq_kernel, cudaFuncAttributeMaxDynamicSharedMemorySize, SMEM_BYTES);
    vq_reset<<<1, 1>>>();
    vq_kernel<<<296, NTHREADS, SMEM_BYTES>>>(z, cb, (float*)d_out, n_rows);
}

// round 13
// speedup vs baseline: 1.8355x; 1.0657x over previous
#include <cuda_runtime.h>

#define DIM      64
#define KC       512
#define ROWS     128          // z rows per tile
#define KCHUNK   128          // codebook codes per smem chunk
#define NCHUNK   (KC / KCHUNK)
#define NTHREADS 256
#define ZS_LD    132          // 132*4B: 16B-aligned rows, conflict-free
#define ES_LD    132
#define SMEM_FLOATS (DIM*ZS_LD + DIM*ES_LD + KC + ROWS)
#define SMEM_BYTES  (SMEM_FLOATS * 4)

// ---- packed f32x2 helpers (ptxas never emits FFMA2 on its own) ----
#define FMA2(acc, a, b) asm("fma.rn.f32x2 %0, %1, %2, %0;" : "+l"(acc) : "l"(a), "l"(b))
#define DUP2(dst, x)    asm("mov.b64 %0, {%1, %1};" : "=l"(dst) : "r"(x))
#define UNPK(lo, hi, v) asm("mov.b64 {%0, %1}, %2;" : "=r"(lo), "=r"(hi) : "l"(v))

__device__ unsigned int g_tile_ctr;

__global__ void vq_reset() { g_tile_ctr = 0; }

__global__ void __launch_bounds__(NTHREADS, 2)
vq_kernel(const float* __restrict__ z, const float* __restrict__ cb,
          float* __restrict__ out, int n_rows) {
    extern __shared__ __align__(16) float sm[];
    float* ZS = sm;                   // [DIM][ZS_LD]  z tile transposed
    float* ES = ZS + DIM * ZS_LD;     // [DIM][ES_LD]  cb chunk transposed
    float* CN = ES + DIM * ES_LD;     // [KC]          ||e_k||^2
    float* ZN = CN + KC;              // [ROWS]        ||z_r||^2
    __shared__ int s_tile;

    const int tid = threadIdx.x;
    const int cx  = tid & 15;         // code group: 8 codes as 2 float4 spans
    const int ry  = tid >> 4;         // row group: 8 rows

    // Codebook norms, reference rounding order (rounded mul, rounded add, d ascending).
    for (int k = tid; k < KC; k += NTHREADS) {
        const float* row = cb + k * DIM;
        float acc = 0.f;
        #pragma unroll 1
        for (int d = 0; d < DIM; d++) {
            float e = row[d];
            acc = __fadd_rn(acc, __fmul_rn(e, e));
        }
        CN[k] = acc;
    }

    const int ntiles = n_rows / ROWS;
    for (;;) {
        __syncthreads();   // prior tile's readers done; CN visible on first pass
        if (tid == 0) s_tile = (int)atomicAdd(&g_tile_ctr, 1u);
        __syncthreads();
        const int tile = s_tile;
        if (tile >= ntiles) break;

        const float4* zt4 = reinterpret_cast<const float4*>(z + (size_t)tile * (ROWS * DIM));
        // Z tile transposed; r-major item map -> conflict-free STS.
        for (int i = tid; i < ROWS * DIM / 4; i += NTHREADS) {
            int r  = i & (ROWS - 1);
            int c4 = i >> 7;
            float4 v = zt4[r * (DIM / 4) + c4];
            int d0 = c4 * 4;
            ZS[(d0 + 0) * ZS_LD + r] = v.x;
            ZS[(d0 + 1) * ZS_LD + r] = v.y;
            ZS[(d0 + 2) * ZS_LD + r] = v.z;
            ZS[(d0 + 3) * ZS_LD + r] = v.w;
        }
        __syncthreads();
        // Row norms: same sequential rounding chain as reference's sum(z*z).
        if (tid < ROWS) {
            float acc = 0.f;
            #pragma unroll 1
            for (int d = 0; d < DIM; d++) {
                float a = ZS[d * ZS_LD + tid];
                acc = __fadd_rn(acc, __fmul_rn(a, a));
            }
            ZN[tid] = acc;
        }
        // (ZN published by the sync at the top of the chunk loop)

        float minv[8]; int mini[8];
        #pragma unroll
        for (int i = 0; i < 8; i++) { minv[i] = __int_as_float(0x7f800000); mini[i] = 0; }

        #pragma unroll 1
        for (int kc = 0; kc < NCHUNK; kc++) {
            __syncthreads();   // prev chunk's ES readers done (also publishes ZN on kc=0)
            const float4* cbc4 =
                reinterpret_cast<const float4*>(cb + (size_t)(kc * KCHUNK) * DIM);
            for (int i = tid; i < KCHUNK * DIM / 4; i += NTHREADS) {
                int kl = i & (KCHUNK - 1);
                int c4 = i >> 7;
                float4 v = cbc4[kl * (DIM / 4) + c4];
                int d0 = c4 * 4;
                ES[(d0 + 0) * ES_LD + kl] = v.x;
                ES[(d0 + 1) * ES_LD + kl] = v.y;
                ES[(d0 + 2) * ES_LD + kl] = v.z;
                ES[(d0 + 3) * ES_LD + kl] = v.w;
            }
            __syncthreads();

            // 8x8 microtile, software-pipelined: loads for d+1 issue before the
            // FMA block for d, covering the 29-cyc LDS latency inside one warp.
            unsigned long long acc2[8][4];
            #pragma unroll
            for (int i = 0; i < 8; i++)
                #pragma unroll
                for (int j = 0; j < 4; j++) acc2[i][j] = 0ull;

            const float* zp = ZS + ry * 8;
            const float* ep = ES + cx * 4;

            float4     a0 = *reinterpret_cast<const float4*>(zp);
            float4     a1 = *reinterpret_cast<const float4*>(zp + 4);
            ulonglong2 b0 = *reinterpret_cast<const ulonglong2*>(ep);
            ulonglong2 b1 = *reinterpret_cast<const ulonglong2*>(ep + 64);

            #pragma unroll 8
            for (int d = 0; d < DIM; d++) {
                const int dn = (d + 1 < DIM) ? d + 1 : d;   // clamped prefetch
                float4     na0 = *reinterpret_cast<const float4*>(zp + dn * ZS_LD);
                float4     na1 = *reinterpret_cast<const float4*>(zp + dn * ZS_LD + 4);
                ulonglong2 nb0 = *reinterpret_cast<const ulonglong2*>(ep + dn * ES_LD);
                ulonglong2 nb1 = *reinterpret_cast<const ulonglong2*>(ep + dn * ES_LD + 64);

                unsigned long long bp[4] = {b0.x, b0.y, b1.x, b1.y};
                float av[8] = {a0.x, a0.y, a0.z, a0.w, a1.x, a1.y, a1.z, a1.w};
                #pragma unroll
                for (int i = 0; i < 8; i++) {
                    unsigned long long ad;
                    DUP2(ad, __float_as_uint(av[i]));
                    #pragma unroll
                    for (int j = 0; j < 4; j++) FMA2(acc2[i][j], ad, bp[j]);
                }
                a0 = na0; a1 = na1; b0 = nb0; b1 = nb1;
            }

            // Epilogue: s = fl(fl(zn - 2*dot) + cn); FFMA(-2,dot,zn) bit-identical since
            // 2*dot is exact. Thread scan ascending k, strict < keeps first index.
            const int kb = kc * KCHUNK + cx * 4;
            float4 c0 = *reinterpret_cast<const float4*>(CN + kb);
            float4 c1 = *reinterpret_cast<const float4*>(CN + kb + 64);
            float cn[8] = {c0.x, c0.y, c0.z, c0.w, c1.x, c1.y, c1.z, c1.w};
            #pragma unroll
            for (int i = 0; i < 8; i++) {
                float zn = ZN[ry * 8 + i];
                #pragma unroll
                for (int j = 0; j < 4; j++) {
                    unsigned int lo, hi;
                    UNPK(lo, hi, acc2[i][j]);
                    float s0 = __fadd_rn(__fmaf_rn(-2.0f, __uint_as_float(lo), zn), cn[2 * j]);
                    float s1 = __fadd_rn(__fmaf_rn(-2.0f, __uint_as_float(hi), zn), cn[2 * j + 1]);
                    int k0 = kb + (j >> 1) * 64 + (j & 1) * 2;
                    if (s0 < minv[i]) { minv[i] = s0; mini[i] = k0; }
                    if (s1 < minv[i]) { minv[i] = s1; mini[i] = k0 + 1; }
                }
            }
        }

        // Reduce across the 16 cx lanes per row group (lower index wins ties).
        #pragma unroll
        for (int i = 0; i < 8; i++) {
            float v  = minv[i];
            int  idx = mini[i];
            #pragma unroll
            for (int off = 8; off > 0; off >>= 1) {
                float vo = __shfl_xor_sync(0xffffffffu, v, off);
                int   io = __shfl_xor_sync(0xffffffffu, idx, off);
                if (vo < v || (vo == v && io < idx)) { v = vo; idx = io; }
            }
            // Output buffer is float32 — exact for idx <= 511.
            if (cx == 0) out[tile * ROWS + ry * 8 + i] = (float)idx;
        }
    }
}

extern "C" void kernel_launch(void* const* d_in, const int* in_sizes, int n_in,
                              void* d_out, int out_size) {
    int cb_idx = (n_in > 1 && in_sizes[1] == KC * DIM) ? 1 : 0;
    int z_idx  = 1 - cb_idx;
    const float* z  = (const float*)d_in[z_idx];    // z_e_x  [32,4096,64] f32
    const float* cb = (const float*)d_in[cb_idx];   // codebook [512,64]  f32
    int n_rows = in_sizes[z_idx] / DIM;             // 131072

    cudaFuncSetAttribute(vq_kernel, cudaFuncAttributeMaxDynamicSharedMemorySize, SMEM_BYTES);
    vq_reset<<<1, 1>>>();
    vq_kernel<<<296, NTHREADS, SMEM_BYTES>>>(z, cb, (float*)d_out, n_rows);
}

// round 14
// speedup vs baseline: 1.9393x; 1.0566x over previous
#include <cuda_runtime.h>

#define DIM      64
#define KC       512
#define ROWS     128          // z rows per tile
#define KCHUNK   128          // codebook codes per smem chunk
#define NCHUNK   (KC / KCHUNK)
#define NTHREADS 128
#define ZS_LD    132          // 132*4B: 16B-aligned rows, conflict-free
#define ES_LD    132
#define SMEM_FLOATS (DIM*ZS_LD + DIM*ES_LD + KC + ROWS)
#define SMEM_BYTES  (SMEM_FLOATS * 4)

// ---- packed f32x2 helpers (ptxas never emits FFMA2 on its own) ----
#define FMA2(acc, a, b) asm("fma.rn.f32x2 %0, %1, %2, %0;" : "+l"(acc) : "l"(a), "l"(b))
#define DUP2(dst, x)    asm("mov.b64 %0, {%1, %1};" : "=l"(dst) : "r"(x))
#define UNPK(lo, hi, v) asm("mov.b64 {%0, %1}, %2;" : "=r"(lo), "=r"(hi) : "l"(v))

__device__ unsigned int g_tile_ctr;

__global__ void vq_reset() { g_tile_ctr = 0; }

__global__ void __launch_bounds__(NTHREADS, 2)
vq_kernel(const float* __restrict__ z, const float* __restrict__ cb,
          float* __restrict__ out, int n_rows) {
    extern __shared__ __align__(16) float sm[];
    float* ZS = sm;                   // [DIM][ZS_LD]  z tile transposed
    float* ES = ZS + DIM * ZS_LD;     // [DIM][ES_LD]  cb chunk transposed
    float* CN = ES + DIM * ES_LD;     // [KC]          ||e_k||^2
    float* ZN = CN + KC;              // [ROWS]        ||z_r||^2
    __shared__ int s_tile;

    const int tid = threadIdx.x;
    const int cx  = tid & 15;         // code group: 8 codes as 2 float4 spans
    const int ry  = tid >> 4;         // row group: 16 rows (8 packed pairs)

    // Codebook norms, reference rounding order (rounded mul, rounded add, d ascending).
    for (int k = tid; k < KC; k += NTHREADS) {
        const float* row = cb + k * DIM;
        float acc = 0.f;
        #pragma unroll 1
        for (int d = 0; d < DIM; d++) {
            float e = row[d];
            acc = __fadd_rn(acc, __fmul_rn(e, e));
        }
        CN[k] = acc;
    }

    const int ntiles = n_rows / ROWS;
    for (;;) {
        __syncthreads();   // prior tile's readers done; CN visible on first pass
        if (tid == 0) s_tile = (int)atomicAdd(&g_tile_ctr, 1u);
        __syncthreads();
        const int tile = s_tile;
        if (tile >= ntiles) break;

        const float4* zt4 = reinterpret_cast<const float4*>(z + (size_t)tile * (ROWS * DIM));
        // Z tile transposed; r-major item map -> conflict-free STS.
        for (int i = tid; i < ROWS * DIM / 4; i += NTHREADS) {
            int r  = i & (ROWS - 1);
            int c4 = i >> 7;
            float4 v = zt4[r * (DIM / 4) + c4];
            int d0 = c4 * 4;
            ZS[(d0 + 0) * ZS_LD + r] = v.x;
            ZS[(d0 + 1) * ZS_LD + r] = v.y;
            ZS[(d0 + 2) * ZS_LD + r] = v.z;
            ZS[(d0 + 3) * ZS_LD + r] = v.w;
        }
        __syncthreads();
        // Row norms: same sequential rounding chain as reference's sum(z*z).
        {
            float acc = 0.f;
            #pragma unroll 1
            for (int d = 0; d < DIM; d++) {
                float a = ZS[d * ZS_LD + tid];
                acc = __fadd_rn(acc, __fmul_rn(a, a));
            }
            ZN[tid] = acc;
        }
        // (ZN published by the sync at the top of the chunk loop)

        float minv[16]; int mini[16];
        #pragma unroll
        for (int i = 0; i < 16; i++) { minv[i] = __int_as_float(0x7f800000); mini[i] = 0; }

        #pragma unroll 1
        for (int kc = 0; kc < NCHUNK; kc++) {
            __syncthreads();   // prev chunk's ES readers done (also publishes ZN on kc=0)
            const float4* cbc4 =
                reinterpret_cast<const float4*>(cb + (size_t)(kc * KCHUNK) * DIM);
            for (int i = tid; i < KCHUNK * DIM / 4; i += NTHREADS) {
                int kl = i & (KCHUNK - 1);
                int c4 = i >> 7;
                float4 v = cbc4[kl * (DIM / 4) + c4];
                int d0 = c4 * 4;
                ES[(d0 + 0) * ES_LD + kl] = v.x;
                ES[(d0 + 1) * ES_LD + kl] = v.y;
                ES[(d0 + 2) * ES_LD + kl] = v.z;
                ES[(d0 + 3) * ES_LD + kl] = v.w;
            }
            __syncthreads();

            // 16x8 microtile, row-pair packed: acc2[rp][c] = rows (2rp,2rp+1), code c.
            // A row-pairs come pre-packed from contiguous ZS rows (no DUP needed);
            // only the 8 B values are duplicated (8 DUP2 per thread-d vs 16 before).
            unsigned long long acc2[8][8];
            #pragma unroll
            for (int i = 0; i < 8; i++)
                #pragma unroll
                for (int j = 0; j < 8; j++) acc2[i][j] = 0ull;

            const float* zp = ZS + ry * 16;
            const float* ep = ES + cx * 4;

            ulonglong2 A0 = *reinterpret_cast<const ulonglong2*>(zp);
            ulonglong2 A1 = *reinterpret_cast<const ulonglong2*>(zp + 4);
            ulonglong2 A2 = *reinterpret_cast<const ulonglong2*>(zp + 8);
            ulonglong2 A3 = *reinterpret_cast<const ulonglong2*>(zp + 12);
            float4     B0 = *reinterpret_cast<const float4*>(ep);
            float4     B1 = *reinterpret_cast<const float4*>(ep + 64);

            #pragma unroll 4
            for (int d = 0; d < DIM; d++) {
                const int dn = (d + 1 < DIM) ? d + 1 : d;   // clamped prefetch
                ulonglong2 nA0 = *reinterpret_cast<const ulonglong2*>(zp + dn * ZS_LD);
                ulonglong2 nA1 = *reinterpret_cast<const ulonglong2*>(zp + dn * ZS_LD + 4);
                ulonglong2 nA2 = *reinterpret_cast<const ulonglong2*>(zp + dn * ZS_LD + 8);
                ulonglong2 nA3 = *reinterpret_cast<const ulonglong2*>(zp + dn * ZS_LD + 12);
                float4     nB0 = *reinterpret_cast<const float4*>(ep + dn * ES_LD);
                float4     nB1 = *reinterpret_cast<const float4*>(ep + dn * ES_LD + 64);

                unsigned long long ap[8] = {A0.x, A0.y, A1.x, A1.y, A2.x, A2.y, A3.x, A3.y};
                float bv[8] = {B0.x, B0.y, B0.z, B0.w, B1.x, B1.y, B1.z, B1.w};
                unsigned long long bd[8];
                #pragma unroll
                for (int c = 0; c < 8; c++) DUP2(bd[c], __float_as_uint(bv[c]));
                #pragma unroll
                for (int rp = 0; rp < 8; rp++)
                    #pragma unroll
                    for (int c = 0; c < 8; c++) FMA2(acc2[rp][c], ap[rp], bd[c]);

                A0 = nA0; A1 = nA1; A2 = nA2; A3 = nA3; B0 = nB0; B1 = nB1;
            }

            // Epilogue: s = fl(fl(zn - 2*dot) + cn); FFMA(-2,dot,zn) bit-identical since
            // 2*dot is exact. Thread scan ascending k (c ascending), strict <.
            const int kb = kc * KCHUNK + cx * 4;
            float4 c0 = *reinterpret_cast<const float4*>(CN + kb);
            float4 c1 = *reinterpret_cast<const float4*>(CN + kb + 64);
            float cn[8] = {c0.x, c0.y, c0.z, c0.w, c1.x, c1.y, c1.z, c1.w};
            #pragma unroll
            for (int rp = 0; rp < 8; rp++) {
                float zn0 = ZN[ry * 16 + 2 * rp];
                float zn1 = ZN[ry * 16 + 2 * rp + 1];
                #pragma unroll
                for (int c = 0; c < 8; c++) {
                    unsigned int lo, hi;
                    UNPK(lo, hi, acc2[rp][c]);
                    float s0 = __fadd_rn(__fmaf_rn(-2.0f, __uint_as_float(lo), zn0), cn[c]);
                    float s1 = __fadd_rn(__fmaf_rn(-2.0f, __uint_as_float(hi), zn1), cn[c]);
                    int k = kb + (c >> 2) * 64 + (c & 3);
                    if (s0 < minv[2 * rp])     { minv[2 * rp]     = s0; mini[2 * rp]     = k; }
                    if (s1 < minv[2 * rp + 1]) { minv[2 * rp + 1] = s1; mini[2 * rp + 1] = k; }
                }
            }
        }

        // Reduce across the 16 cx lanes per row (lower index wins ties).
        #pragma unroll
        for (int i = 0; i < 16; i++) {
            float v  = minv[i];
            int  idx = mini[i];
            #pragma unroll
            for (int off = 8; off > 0; off >>= 1) {
                float vo = __shfl_xor_sync(0xffffffffu, v, off);
                int   io = __shfl_xor_sync(0xffffffffu, idx, off);
                if (vo < v || (vo == v && io < idx)) { v = vo; idx = io; }
            }
            // Output buffer is float32 — exact for idx <= 511.
            if (cx == 0) out[tile * ROWS + ry * 16 + i] = (float)idx;
        }
    }
}

extern "C" void kernel_launch(void* const* d_in, const int* in_sizes, int n_in,
                              void* d_out, int out_size) {
    int cb_idx = (n_in > 1 && in_sizes[1] == KC * DIM) ? 1 : 0;
    int z_idx  = 1 - cb_idx;
    const float* z  = (const float*)d_in[z_idx];    // z_e_x  [32,4096,64] f32
    const float* cb = (const float*)d_in[cb_idx];   // codebook [512,64]  f32
    int n_rows = in_sizes[z_idx] / DIM;             // 131072

    cudaFuncSetAttribute(vq_kernel, cudaFuncAttributeMaxDynamicSharedMemorySize, SMEM_BYTES);
    vq_reset<<<1, 1>>>();
    vq_kernel<<<296, NTHREADS, SMEM_BYTES>>>(z, cb, (float*)d_out, n_rows);
}